// round 8
// baseline (speedup 1.0000x reference)
#include <cuda_runtime.h>
#include <cuda_bf16.h>
#include <cstdint>

#define IN_F     4096
#define OUT_F    11008
#define MROWS    32
#define GRP      128
#define KSPLIT   2
#define KPER     (IN_F / KSPLIT)          // 2048
#define NGROUPS  (KPER / GRP)             // 16
#define NTILE    64
#define CTAS_COL (OUT_F / NTILE)          // 172
#define THREADS  128

#define XROW_B   272                      // x row: 256B data + 16B pad (odd 16B count -> ldmatrix conflict-free)

__device__ __forceinline__ float bfr(float v) {
    return __bfloat162float(__float2bfloat16(v));
}

__device__ __forceinline__ uint32_t pack_bf16x2(float hi, float lo) {
    uint32_t r;
    asm("cvt.rn.bf16x2.f32 %0, %1, %2;" : "=r"(r) : "f"(hi), "f"(lo));
    return r;
}

__device__ __forceinline__ void hmma(float c[4], const uint32_t a[4],
                                     uint32_t b0, uint32_t b1) {
    asm volatile(
        "mma.sync.aligned.m16n8k16.row.col.f32.bf16.bf16.f32 "
        "{%0,%1,%2,%3}, {%4,%5,%6,%7}, {%8,%9}, {%0,%1,%2,%3};"
        : "+f"(c[0]), "+f"(c[1]), "+f"(c[2]), "+f"(c[3])
        : "r"(a[0]), "r"(a[1]), "r"(a[2]), "r"(a[3]), "r"(b0), "r"(b1));
}

// Load the 4 int32s backing one (ks, t) B fragment straight from qweight.
// Coalesced: per tig-group, 8 gid-threads read 8 consecutive int32 (one sector).
__device__ __forceinline__ void load_b(int b[4], const int* __restrict__ qweight,
                                       int kb, int ks, int tig, int ncol) {
    const int* p = qweight + (size_t)(kb + 16 * ks + 2 * tig) * OUT_F + ncol;
    b[0] = p[0];                       // k = 16ks + 2tig
    b[1] = p[OUT_F];                   // k+1
    b[2] = p[(size_t)8 * OUT_F];       // k+8
    b[3] = p[(size_t)9 * OUT_F];       // k+9
}

// ---------------------------------------------------------------------------
__global__ void init_out_kernel(const float* __restrict__ bias,
                                float* __restrict__ out)
{
    int o = blockIdx.x * blockDim.x + threadIdx.x;
    if (o < OUT_F) {
        float b = bfr(bias[o]);
        #pragma unroll
        for (int s = 0; s < MROWS; s++)
            out[(size_t)s * OUT_F + o] = b;
    }
}

// ---------------------------------------------------------------------------
// Per CTA: 64 output cols x 2048 K; warp w owns local cols [16w, 16w+16).
// x tile staged bf16 in SMEM (ldmatrix A); B fragments (qw - qz, 5-bit exact
// in bf16) loaded DIRECTLY from global into registers -> zero W SMEM traffic.
// Per-group scale applied in register epilogue on C-fragment columns (exact).
// ---------------------------------------------------------------------------
__global__ void __launch_bounds__(THREADS)
qmain(const float* __restrict__ x, const int* __restrict__ qweight,
      const int* __restrict__ qzeros, const float* __restrict__ scales,
      float* __restrict__ out)
{
    __shared__ __align__(16) uint8_t xs_raw[MROWS * XROW_B];   // 8704 B

    uint32_t xs_b;
    asm("{ .reg .u64 t; cvta.to.shared.u64 t, %1; cvt.u32.u64 %0, t; }"
        : "=r"(xs_b) : "l"(xs_raw));

    const int tid   = threadIdx.x;
    const int w     = tid >> 5;
    const int l     = tid & 31;
    const int bx    = blockIdx.x;
    const int ctile = bx % CTAS_COL;
    const int kq    = bx / CTAS_COL;
    const int o0    = ctile * NTILE;

    const int gid = l >> 2;                // fragment group id
    const int tig = l & 3;                 // thread-in-group
    const int nc0 = o0 + w * 16 + gid;     // B column, t=0
    const int nc1 = nc0 + 8;               // B column, t=1
    const int cc  = o0 + w * 16 + 2 * tig; // C column base (this thread's outputs)

    // ldmatrix A lane address: row = l&15, k-chunk(8) = l>>4
    const uint32_t a_lane_off = (uint32_t)(l & 15) * XROW_B + (uint32_t)(l >> 4) * 16;

    float ct[2][2][4];
    #pragma unroll
    for (int mi = 0; mi < 2; mi++)
        #pragma unroll
        for (int t = 0; t < 2; t++)
            #pragma unroll
            for (int r = 0; r < 4; r++) ct[mi][t][r] = 0.0f;

    for (int g = 0; g < NGROUPS; g++) {
        const int kb = kq * KPER + g * GRP;
        const int gg = kb >> 7;

        // per-group zero for this thread's B columns
        const int qz0 = qzeros[(size_t)gg * OUT_F + nc0];
        const int qz1 = qzeros[(size_t)gg * OUT_F + nc1];

        // prefetch B for ks=0 (independent of SMEM -> overlaps x staging)
        int bc0[4], bc1[4];
        load_b(bc0, qweight, kb, 0, tig, nc0);
        load_b(bc1, qweight, kb, 0, tig, nc1);

        __syncthreads();   // prior group's xs reads complete

        // ---- stage x[0:32][kb:kb+128] -> bf16, STS.64 ----
        #pragma unroll
        for (int j = 0; j < 8; j++) {
            int idx = tid + THREADS * j;      // 0..1023
            int s   = idx >> 5;               // row 0..31
            int kq4 = idx & 31;               // float4 index in row
            float4 v = *(const float4*)(x + (size_t)s * IN_F + kb + 4 * kq4);
            uint32_t p0 = pack_bf16x2(v.y, v.x);
            uint32_t p1 = pack_bf16x2(v.w, v.z);
            uint32_t a = xs_b + (uint32_t)s * XROW_B + (uint32_t)kq4 * 8;
            asm volatile("st.shared.v2.b32 [%0], {%1,%2};" :: "r"(a), "r"(p0), "r"(p1));
        }
        __syncthreads();

        float cg[2][2][4];
        #pragma unroll
        for (int mi = 0; mi < 2; mi++)
            #pragma unroll
            for (int t = 0; t < 2; t++)
                #pragma unroll
                for (int r = 0; r < 4; r++) cg[mi][t][r] = 0.0f;

        #pragma unroll
        for (int ks = 0; ks < 8; ks++) {
            // prefetch next kstep's B while this kstep computes
            int bn0[4], bn1[4];
            if (ks < 7) {
                load_b(bn0, qweight, kb, ks + 1, tig, nc0);
                load_b(bn1, qweight, kb, ks + 1, tig, nc1);
            }

            uint32_t a0[4], a1[4];
            uint32_t addr0 = xs_b + a_lane_off + (uint32_t)ks * 32;
            uint32_t addr1 = addr0 + 16u * XROW_B;
            asm volatile("ldmatrix.sync.aligned.m8n8.x4.shared.b16 {%0,%1,%2,%3}, [%4];"
                         : "=r"(a0[0]), "=r"(a0[1]), "=r"(a0[2]), "=r"(a0[3]) : "r"(addr0));
            asm volatile("ldmatrix.sync.aligned.m8n8.x4.shared.b16 {%0,%1,%2,%3}, [%4];"
                         : "=r"(a1[0]), "=r"(a1[1]), "=r"(a1[2]), "=r"(a1[3]) : "r"(addr1));

            // convert + MMA, t = 0
            {
                uint32_t b0 = pack_bf16x2((float)(bc0[1] - qz0), (float)(bc0[0] - qz0));
                uint32_t b1 = pack_bf16x2((float)(bc0[3] - qz0), (float)(bc0[2] - qz0));
                hmma(cg[0][0], a0, b0, b1);
                hmma(cg[1][0], a1, b0, b1);
            }
            // t = 1
            {
                uint32_t b0 = pack_bf16x2((float)(bc1[1] - qz1), (float)(bc1[0] - qz1));
                uint32_t b1 = pack_bf16x2((float)(bc1[3] - qz1), (float)(bc1[2] - qz1));
                hmma(cg[0][1], a0, b0, b1);
                hmma(cg[1][1], a1, b0, b1);
            }

            if (ks < 7) {
                #pragma unroll
                for (int r = 0; r < 4; r++) { bc0[r] = bn0[r]; bc1[r] = bn1[r]; }
            }
        }

        // ---- per-group scale epilogue on C-fragment columns (2*tig based) ----
        const float sA = bfr(scales[(size_t)gg * OUT_F + cc]);        // t=0, col 2tig
        const float sB = bfr(scales[(size_t)gg * OUT_F + cc + 1]);    // t=0, col 2tig+1
        const float sC = bfr(scales[(size_t)gg * OUT_F + cc + 8]);    // t=1, col 2tig
        const float sD = bfr(scales[(size_t)gg * OUT_F + cc + 9]);    // t=1, col 2tig+1
        #pragma unroll
        for (int mi = 0; mi < 2; mi++) {
            ct[mi][0][0] = fmaf(cg[mi][0][0], sA, ct[mi][0][0]);
            ct[mi][0][1] = fmaf(cg[mi][0][1], sB, ct[mi][0][1]);
            ct[mi][0][2] = fmaf(cg[mi][0][2], sA, ct[mi][0][2]);
            ct[mi][0][3] = fmaf(cg[mi][0][3], sB, ct[mi][0][3]);
            ct[mi][1][0] = fmaf(cg[mi][1][0], sC, ct[mi][1][0]);
            ct[mi][1][1] = fmaf(cg[mi][1][1], sD, ct[mi][1][1]);
            ct[mi][1][2] = fmaf(cg[mi][1][2], sC, ct[mi][1][2]);
            ct[mi][1][3] = fmaf(cg[mi][1][3], sD, ct[mi][1][3]);
        }
    }

    // ---- K-split reduction into bias-initialized output ----
    #pragma unroll
    for (int mi = 0; mi < 2; mi++) {
        int s0 = mi * 16 + gid;
        #pragma unroll
        for (int t = 0; t < 2; t++) {
            int oc = cc + t * 8;
            atomicAdd(&out[(size_t)s0 * OUT_F + oc],           ct[mi][t][0]);
            atomicAdd(&out[(size_t)s0 * OUT_F + oc + 1],       ct[mi][t][1]);
            atomicAdd(&out[(size_t)(s0 + 8) * OUT_F + oc],     ct[mi][t][2]);
            atomicAdd(&out[(size_t)(s0 + 8) * OUT_F + oc + 1], ct[mi][t][3]);
        }
    }
}

// ---------------------------------------------------------------------------
// inputs: x f32[1,32,4096], qweight i32[4096,11008], qzeros i32[32,11008],
//         scales f32[32,11008], bias f32[11008]; output f32[1,32,11008]
// ---------------------------------------------------------------------------
extern "C" void kernel_launch(void* const* d_in, const int* in_sizes, int n_in,
                              void* d_out, int out_size)
{
    const float* x       = (const float*)d_in[0];
    const int*   qweight = (const int*)  d_in[1];
    const int*   qzeros  = (const int*)  d_in[2];
    const float* scales  = (const float*)d_in[3];
    const float* bias    = (const float*)d_in[4];
    float*       out     = (float*)d_out;

    init_out_kernel<<<(OUT_F + 255) / 256, 256>>>(bias, out);
    qmain<<<CTAS_COL * KSPLIT, THREADS>>>(x, qweight, qzeros, scales, out);
}

// round 9
// speedup vs baseline: 1.6011x; 1.6011x over previous
#include <cuda_runtime.h>
#include <cuda_bf16.h>
#include <cstdint>

#define IN_F     4096
#define OUT_F    11008
#define MROWS    32
#define GRP      128
#define KSPLIT   4
#define KPER     (IN_F / KSPLIT)          // 1024
#define NGROUPS  (KPER / GRP)             // 8
#define STAGE_K  64
#define NSTAGES  (KPER / STAGE_K)         // 16
#define NTILE    64
#define CTAS_COL (OUT_F / NTILE)          // 172
#define THREADS  128

#define XROW_B   272                      // x row: 256B bf16 + 16B pad
#define WROW_B   272                      // raw W row: 64 int32 (256B) + 16B pad -> conflict-free LDS
#define WSTAGE_B (STAGE_K * WROW_B)       // 17408

__device__ __forceinline__ float bfr(float v) {
    return __bfloat162float(__float2bfloat16(v));
}

__device__ __forceinline__ uint32_t pack_bf16x2(float hi, float lo) {
    uint32_t r;
    asm("cvt.rn.bf16x2.f32 %0, %1, %2;" : "=r"(r) : "f"(hi), "f"(lo));
    return r;
}

__device__ __forceinline__ void hmma(float c[4], const uint32_t a[4],
                                     uint32_t b0, uint32_t b1) {
    asm volatile(
        "mma.sync.aligned.m16n8k16.row.col.f32.bf16.bf16.f32 "
        "{%0,%1,%2,%3}, {%4,%5,%6,%7}, {%8,%9}, {%0,%1,%2,%3};"
        : "+f"(c[0]), "+f"(c[1]), "+f"(c[2]), "+f"(c[3])
        : "r"(a[0]), "r"(a[1]), "r"(a[2]), "r"(a[3]), "r"(b0), "r"(b1));
}

// ---------------------------------------------------------------------------
__global__ void init_out_kernel(const float* __restrict__ bias,
                                float* __restrict__ out)
{
    int o = blockIdx.x * blockDim.x + threadIdx.x;
    if (o < OUT_F) {
        float b = bfr(bias[o]);
        #pragma unroll
        for (int s = 0; s < MROWS; s++)
            out[(size_t)s * OUT_F + o] = b;
    }
}

// ---------------------------------------------------------------------------
// Per CTA: 64 output cols x 1024 K, in 16 stages of 64 k-rows.
// Raw int32 qweight tiles stream into double-buffered SMEM via cp.async.cg
// (overlapping MMA); B fragments convert on-read (qw-qz is 5-bit, bf16-exact);
// per-group scale in register epilogue on C columns (exact).
// ---------------------------------------------------------------------------
__global__ void __launch_bounds__(THREADS)
qmain(const float* __restrict__ x, const int* __restrict__ qweight,
      const int* __restrict__ qzeros, const float* __restrict__ scales,
      float* __restrict__ out)
{
    __shared__ __align__(16) uint8_t xs_raw[MROWS * XROW_B];     //  8704 B
    __shared__ __align__(16) uint8_t ws_raw[2 * WSTAGE_B];       // 34816 B

    uint32_t xs_b, ws_b;
    asm("{ .reg .u64 t; cvta.to.shared.u64 t, %1; cvt.u32.u64 %0, t; }"
        : "=r"(xs_b) : "l"(xs_raw));
    asm("{ .reg .u64 t; cvta.to.shared.u64 t, %1; cvt.u32.u64 %0, t; }"
        : "=r"(ws_b) : "l"(ws_raw));

    const int tid   = threadIdx.x;
    const int w     = tid >> 5;
    const int l     = tid & 31;
    const int bx    = blockIdx.x;
    const int ctile = bx % CTAS_COL;
    const int kq    = bx / CTAS_COL;
    const int o0    = ctile * NTILE;
    const int k0    = kq * KPER;

    const int gid = l >> 2;                // fragment group id
    const int tig = l & 3;                 // thread-in-group
    const int nc0 = o0 + w * 16 + gid;     // B column, t=0
    const int nc1 = nc0 + 8;               // B column, t=1
    const int cc  = o0 + w * 16 + 2 * tig; // C column base

    // ldmatrix A lane address: row = l&15, k-chunk(8) = l>>4
    const uint32_t a_lane_off = (uint32_t)(l & 15) * XROW_B + (uint32_t)(l >> 4) * 16;

    // B read base offsets in the raw stage buffer: row = 16*ks + 2*tig (+1,+8,+9)
    const uint32_t b_off0 = (uint32_t)(2 * tig) * WROW_B + (uint32_t)(w * 16 + gid) * 4;     // t=0
    const uint32_t b_off1 = b_off0 + 32;                                                      // t=1 (+8 cols)

    // cp.async mapping: 8 ops/thread, each 16B; 16 threads cover one k-row
    const int cp_row0 = tid >> 4;          // + 8*j
    const int cp_seg  = tid & 15;          // 16B segment in row

    float ct[2][2][4];
    #pragma unroll
    for (int mi = 0; mi < 2; mi++)
        #pragma unroll
        for (int t = 0; t < 2; t++)
            #pragma unroll
            for (int r = 0; r < 4; r++) ct[mi][t][r] = 0.0f;

    float cg[2][2][4];
    #pragma unroll
    for (int mi = 0; mi < 2; mi++)
        #pragma unroll
        for (int t = 0; t < 2; t++)
            #pragma unroll
            for (int r = 0; r < 4; r++) cg[mi][t][r] = 0.0f;

    int qz0 = 0, qz1 = 0;

    // ---- prologue: issue stage 0 copy ----
    {
        const int* gsrc = qweight + (size_t)k0 * OUT_F + o0;
        #pragma unroll
        for (int j = 0; j < 8; j++) {
            int row = cp_row0 + 8 * j;
            uint32_t dst = ws_b + (uint32_t)row * WROW_B + (uint32_t)cp_seg * 16;
            const int* src = gsrc + (size_t)row * OUT_F + cp_seg * 4;
            asm volatile("cp.async.cg.shared.global [%0], [%1], 16;"
                         :: "r"(dst), "l"(src));
        }
        asm volatile("cp.async.commit_group;" ::: "memory");
    }

    for (int st = 0; st < NSTAGES; st++) {
        const int g  = st >> 1;
        const int gg = (k0 >> 7) + g;           // global group index
        const int kb = k0 + g * GRP;            // group k base

        __syncthreads();   // MMA(st-1) reads complete (xs + W buffer reuse safe)

        // ---- issue cp.async for stage st+1 ----
        if (st + 1 < NSTAGES) {
            const uint32_t wdst = ws_b + (uint32_t)((st + 1) & 1) * WSTAGE_B;
            const int* gsrc = qweight + (size_t)(k0 + (st + 1) * STAGE_K) * OUT_F + o0;
            #pragma unroll
            for (int j = 0; j < 8; j++) {
                int row = cp_row0 + 8 * j;
                uint32_t dst = wdst + (uint32_t)row * WROW_B + (uint32_t)cp_seg * 16;
                const int* src = gsrc + (size_t)row * OUT_F + cp_seg * 4;
                asm volatile("cp.async.cg.shared.global [%0], [%1], 16;"
                             :: "r"(dst), "l"(src));
            }
            asm volatile("cp.async.commit_group;" ::: "memory");
        }

        // ---- even stage: stage x tile for this group + load qzeros ----
        if ((st & 1) == 0) {
            #pragma unroll
            for (int j = 0; j < 8; j++) {
                int idx = tid + THREADS * j;      // 0..1023
                int s   = idx >> 5;               // row 0..31
                int kq4 = idx & 31;               // float4 index
                float4 v = *(const float4*)(x + (size_t)s * IN_F + kb + 4 * kq4);
                uint32_t p0 = pack_bf16x2(v.y, v.x);
                uint32_t p1 = pack_bf16x2(v.w, v.z);
                uint32_t a = xs_b + (uint32_t)s * XROW_B + (uint32_t)kq4 * 8;
                asm volatile("st.shared.v2.b32 [%0], {%1,%2};" :: "r"(a), "r"(p0), "r"(p1));
            }
            qz0 = qzeros[(size_t)gg * OUT_F + nc0];
            qz1 = qzeros[(size_t)gg * OUT_F + nc1];
        }

        // wait for stage st's copy (leave st+1 in flight)
        if (st + 1 < NSTAGES) {
            asm volatile("cp.async.wait_group 1;" ::: "memory");
        } else {
            asm volatile("cp.async.wait_group 0;" ::: "memory");
        }
        __syncthreads();   // copies + xs visible to all threads

        const uint32_t wbuf = ws_b + (uint32_t)(st & 1) * WSTAGE_B;

        // ---- 4 k16-steps of this stage ----
        #pragma unroll
        for (int ksl = 0; ksl < 4; ksl++) {
            const int ks = 4 * (st & 1) + ksl;    // kstep within group (for xs)

            uint32_t a0[4], a1[4];
            uint32_t addr0 = xs_b + a_lane_off + (uint32_t)ks * 32;
            uint32_t addr1 = addr0 + 16u * XROW_B;
            asm volatile("ldmatrix.sync.aligned.m8n8.x4.shared.b16 {%0,%1,%2,%3}, [%4];"
                         : "=r"(a0[0]), "=r"(a0[1]), "=r"(a0[2]), "=r"(a0[3]) : "r"(addr0));
            asm volatile("ldmatrix.sync.aligned.m8n8.x4.shared.b16 {%0,%1,%2,%3}, [%4];"
                         : "=r"(a1[0]), "=r"(a1[1]), "=r"(a1[2]), "=r"(a1[3]) : "r"(addr1));

            const uint32_t rb = wbuf + (uint32_t)(16 * ksl) * WROW_B;

            // t = 0: rows 2tig, 2tig+1, 2tig+8, 2tig+9 at col gid
            {
                int v0, v1, v2, v3;
                asm volatile("ld.shared.b32 %0, [%1];" : "=r"(v0) : "r"(rb + b_off0));
                asm volatile("ld.shared.b32 %0, [%1];" : "=r"(v1) : "r"(rb + b_off0 + WROW_B));
                asm volatile("ld.shared.b32 %0, [%1];" : "=r"(v2) : "r"(rb + b_off0 + 8 * WROW_B));
                asm volatile("ld.shared.b32 %0, [%1];" : "=r"(v3) : "r"(rb + b_off0 + 9 * WROW_B));
                uint32_t b0 = pack_bf16x2((float)(v1 - qz0), (float)(v0 - qz0));
                uint32_t b1 = pack_bf16x2((float)(v3 - qz0), (float)(v2 - qz0));
                hmma(cg[0][0], a0, b0, b1);
                hmma(cg[1][0], a1, b0, b1);
            }
            // t = 1
            {
                int v0, v1, v2, v3;
                asm volatile("ld.shared.b32 %0, [%1];" : "=r"(v0) : "r"(rb + b_off1));
                asm volatile("ld.shared.b32 %0, [%1];" : "=r"(v1) : "r"(rb + b_off1 + WROW_B));
                asm volatile("ld.shared.b32 %0, [%1];" : "=r"(v2) : "r"(rb + b_off1 + 8 * WROW_B));
                asm volatile("ld.shared.b32 %0, [%1];" : "=r"(v3) : "r"(rb + b_off1 + 9 * WROW_B));
                uint32_t b0 = pack_bf16x2((float)(v1 - qz1), (float)(v0 - qz1));
                uint32_t b1 = pack_bf16x2((float)(v3 - qz1), (float)(v2 - qz1));
                hmma(cg[0][1], a0, b0, b1);
                hmma(cg[1][1], a1, b0, b1);
            }
        }

        // ---- odd stage: group finished -> scale epilogue on C columns ----
        if (st & 1) {
            const float sA = bfr(scales[(size_t)gg * OUT_F + cc]);
            const float sB = bfr(scales[(size_t)gg * OUT_F + cc + 1]);
            const float sC = bfr(scales[(size_t)gg * OUT_F + cc + 8]);
            const float sD = bfr(scales[(size_t)gg * OUT_F + cc + 9]);
            #pragma unroll
            for (int mi = 0; mi < 2; mi++) {
                ct[mi][0][0] = fmaf(cg[mi][0][0], sA, ct[mi][0][0]);
                ct[mi][0][1] = fmaf(cg[mi][0][1], sB, ct[mi][0][1]);
                ct[mi][0][2] = fmaf(cg[mi][0][2], sA, ct[mi][0][2]);
                ct[mi][0][3] = fmaf(cg[mi][0][3], sB, ct[mi][0][3]);
                ct[mi][1][0] = fmaf(cg[mi][1][0], sC, ct[mi][1][0]);
                ct[mi][1][1] = fmaf(cg[mi][1][1], sD, ct[mi][1][1]);
                ct[mi][1][2] = fmaf(cg[mi][1][2], sC, ct[mi][1][2]);
                ct[mi][1][3] = fmaf(cg[mi][1][3], sD, ct[mi][1][3]);
                #pragma unroll
                for (int t = 0; t < 2; t++)
                    #pragma unroll
                    for (int r = 0; r < 4; r++) cg[mi][t][r] = 0.0f;
            }
        }
    }

    // ---- K-split reduction into bias-initialized output ----
    #pragma unroll
    for (int mi = 0; mi < 2; mi++) {
        int s0 = mi * 16 + gid;
        #pragma unroll
        for (int t = 0; t < 2; t++) {
            int oc = cc + t * 8;
            atomicAdd(&out[(size_t)s0 * OUT_F + oc],           ct[mi][t][0]);
            atomicAdd(&out[(size_t)s0 * OUT_F + oc + 1],       ct[mi][t][1]);
            atomicAdd(&out[(size_t)(s0 + 8) * OUT_F + oc],     ct[mi][t][2]);
            atomicAdd(&out[(size_t)(s0 + 8) * OUT_F + oc + 1], ct[mi][t][3]);
        }
    }
}

// ---------------------------------------------------------------------------
// inputs: x f32[1,32,4096], qweight i32[4096,11008], qzeros i32[32,11008],
//         scales f32[32,11008], bias f32[11008]; output f32[1,32,11008]
// ---------------------------------------------------------------------------
extern "C" void kernel_launch(void* const* d_in, const int* in_sizes, int n_in,
                              void* d_out, int out_size)
{
    const float* x       = (const float*)d_in[0];
    const int*   qweight = (const int*)  d_in[1];
    const int*   qzeros  = (const int*)  d_in[2];
    const float* scales  = (const float*)d_in[3];
    const float* bias    = (const float*)d_in[4];
    float*       out     = (float*)d_out;

    init_out_kernel<<<(OUT_F + 255) / 256, 256>>>(bias, out);
    qmain<<<CTAS_COL * KSPLIT, THREADS>>>(x, qweight, qzeros, scales, out);
}